// round 5
// baseline (speedup 1.0000x reference)
#include <cuda_runtime.h>

// NNUE batched eval: B rows, per-row
//   w_ = Ww @ [white,black] + bw ; b_ = Wb @ [black,white] + bb   (each 32)
//   base = relu(pov*[w_,b_] + (1-pov)*[b_,w_])                     (64)
//   x1 = relu(W0 @ base + b0)  (32);  x2 = relu(W1 @ x1 + b1) (32)
//   y  = W2 @ [x1,x2] + b2
//
// Strategy: fuse the two feature GEMMs into one X[B,98] @ Wcat[98,64] with
// columns rearranged once by a prep kernel into __device__ scratch. Main
// kernel: 1 thread = 1 row, weights broadcast from shared, accumulators as
// packed f32x2 pairs driven by fma.rn.f32x2 (2 MACs/instr).

#define HALF 49
#define INW  98
#define TPB  128
#define ROWSB 128

// ---- __device__ scratch (allocation-free, prep kernel fills it) ----
__device__ float g_Wcat[INW * 64];   // [k][j] j<32: Ww col; j>=32: Wb col (halves swapped)
__device__ float g_W0t[64 * 32];     // [j][i] = W0[i][j]
__device__ float g_W1t[32 * 32];     // [j][i] = W1[i][j]
__device__ float g_misc[193];        // bcat[64], b0[32], b1[32], W2[64], b2[1]

__global__ void prep_kernel(const float* __restrict__ Ww, const float* __restrict__ bw,
                            const float* __restrict__ Wb, const float* __restrict__ bb,
                            const float* __restrict__ W0, const float* __restrict__ b0,
                            const float* __restrict__ W1, const float* __restrict__ b1,
                            const float* __restrict__ W2, const float* __restrict__ b2) {
    int t = threadIdx.x;
    // Wcat: X row = [white(0..48), black(49..97)]
    //  j<32 : coeff of X[k] in w_ is Ww[j][k]                  (Ww sees [white,black])
    //  j>=32: coeff of X[k] in b_ is Wb[j-32][(k+49) mod 98]   (Wb sees [black,white])
    for (int idx = t; idx < INW * 64; idx += blockDim.x) {
        int k = idx / 64, j = idx % 64;
        float v;
        if (j < 32) {
            v = Ww[j * INW + k];
        } else {
            int jj = j - 32;
            v = (k < HALF) ? Wb[jj * INW + k + HALF] : Wb[jj * INW + k - HALF];
        }
        g_Wcat[idx] = v;
    }
    for (int idx = t; idx < 64 * 32; idx += blockDim.x) {
        int j = idx / 32, i = idx % 32;
        g_W0t[idx] = W0[i * 64 + j];
    }
    for (int idx = t; idx < 32 * 32; idx += blockDim.x) {
        int j = idx / 32, i = idx % 32;
        g_W1t[idx] = W1[i * 32 + j];
    }
    for (int i = t; i < 193; i += blockDim.x) {
        float v;
        if (i < 32)        v = bw[i];
        else if (i < 64)   v = bb[i - 32];
        else if (i < 96)   v = b0[i - 64];
        else if (i < 128)  v = b1[i - 96];
        else if (i < 192)  v = W2[i - 128];
        else               v = b2[0];
        g_misc[i] = v;
    }
}

// ---- packed f32x2 helpers ----
#define PACK2F(dst, fa, fb) do {                                             \
    unsigned int _lo = __float_as_uint(fa), _hi = __float_as_uint(fb);       \
    asm("mov.b64 %0, {%1, %2};" : "=l"(dst) : "r"(_lo), "r"(_hi));           \
} while (0)

#define BCAST2F(dst, fa) do {                                                \
    unsigned int _v = __float_as_uint(fa);                                   \
    asm("mov.b64 %0, {%1, %1};" : "=l"(dst) : "r"(_v));                      \
} while (0)

#define UNPACK2F(fa, fb, src) do {                                           \
    unsigned int _lo, _hi;                                                   \
    asm("mov.b64 {%0, %1}, %2;" : "=r"(_lo), "=r"(_hi) : "l"(src));          \
    fa = __uint_as_float(_lo); fb = __uint_as_float(_hi);                    \
} while (0)

#define FMA2(acc, x2, w2) \
    asm("fma.rn.f32x2 %0, %1, %2, %0;" : "+l"(acc) : "l"(x2), "l"(w2))

__global__ __launch_bounds__(TPB)
void nnue_kernel(const float* __restrict__ pov,
                 const float* __restrict__ white,
                 const float* __restrict__ black,
                 float* __restrict__ out, int B) {
    extern __shared__ float sh[];
    float* xs  = sh;                    // ROWSB * 99 (odd stride -> conflict-free LDS)
    float* sW  = xs + ROWSB * 99;       // 98*64
    float* sW0 = sW + INW * 64;         // 64*32
    float* sW1 = sW0 + 64 * 32;         // 32*32
    float* sM  = sW1 + 32 * 32;         // 193

    const int tid = threadIdx.x;
    const int r0  = blockIdx.x * ROWSB;
    const int nrows = min(ROWSB, B - r0);

    // stage weights (coalesced from prepped scratch, L2-resident)
    for (int i = tid; i < INW * 64; i += TPB) sW[i]  = g_Wcat[i];
    for (int i = tid; i < 64 * 32;  i += TPB) sW0[i] = g_W0t[i];
    for (int i = tid; i < 32 * 32;  i += TPB) sW1[i] = g_W1t[i];
    for (int i = tid; i < 193;      i += TPB) sM[i]  = g_misc[i];

    // stage inputs (fully coalesced global reads)
    {
        const float* wp = white + (size_t)r0 * HALF;
        const float* bp = black + (size_t)r0 * HALF;
        int n = nrows * HALF;
        for (int i = tid; i < n; i += TPB) {
            int r = i / HALF, k = i - r * HALF;
            xs[r * 99 + k]        = wp[i];
            xs[r * 99 + HALF + k] = bp[i];
        }
    }
    __syncthreads();

    if (tid >= nrows) return;

    const float p = pov[r0 + tid];

    // ---- fused feature-transform GEMM: acc[j] = pair (2j, 2j+1) of 64-wide out ----
    unsigned long long acc[32];
#pragma unroll
    for (int j = 0; j < 32; j++) PACK2F(acc[j], sM[2 * j], sM[2 * j + 1]);

    const float* xrow = xs + tid * 99;
#pragma unroll 2
    for (int k = 0; k < INW; k++) {
        unsigned long long x2;
        BCAST2F(x2, xrow[k]);
        const unsigned long long* wr =
            reinterpret_cast<const unsigned long long*>(sW + k * 64);
#pragma unroll
        for (int j = 0; j < 32; j++) FMA2(acc[j], x2, wr[j]);
    }

    float f[64];
#pragma unroll
    for (int j = 0; j < 32; j++) UNPACK2F(f[2 * j], f[2 * j + 1], acc[j]);

    // ---- pov blend + relu: base[j] = relu(p*w_ + (1-p)*b_), base[32+j] swapped ----
    const float q = 1.0f - p;
    float base[64];
#pragma unroll
    for (int j = 0; j < 32; j++) {
        float w = f[j], b = f[32 + j];
        base[j]      = fmaxf(fmaf(p, w, q * b), 0.0f);
        base[32 + j] = fmaxf(fmaf(p, b, q * w), 0.0f);
    }

    // ---- L0: x1 = relu(W0 @ base + b0) ----
    unsigned long long a0[16];
#pragma unroll
    for (int i = 0; i < 16; i++) PACK2F(a0[i], sM[64 + 2 * i], sM[64 + 2 * i + 1]);
    const unsigned long long* W0p = reinterpret_cast<const unsigned long long*>(sW0);
#pragma unroll
    for (int j = 0; j < 64; j++) {
        unsigned long long x2;
        BCAST2F(x2, base[j]);
#pragma unroll
        for (int i = 0; i < 16; i++) FMA2(a0[i], x2, W0p[j * 16 + i]);
    }
    float x1[32];
#pragma unroll
    for (int i = 0; i < 16; i++) {
        float lo, hi; UNPACK2F(lo, hi, a0[i]);
        x1[2 * i]     = fmaxf(lo, 0.0f);
        x1[2 * i + 1] = fmaxf(hi, 0.0f);
    }

    // ---- L1: x2v = relu(W1 @ x1 + b1) ----
    unsigned long long a1[16];
#pragma unroll
    for (int i = 0; i < 16; i++) PACK2F(a1[i], sM[96 + 2 * i], sM[96 + 2 * i + 1]);
    const unsigned long long* W1p = reinterpret_cast<const unsigned long long*>(sW1);
#pragma unroll
    for (int j = 0; j < 32; j++) {
        unsigned long long x2;
        BCAST2F(x2, x1[j]);
#pragma unroll
        for (int i = 0; i < 16; i++) FMA2(a1[i], x2, W1p[j * 16 + i]);
    }
    float x2v[32];
#pragma unroll
    for (int i = 0; i < 16; i++) {
        float lo, hi; UNPACK2F(lo, hi, a1[i]);
        x2v[2 * i]     = fmaxf(lo, 0.0f);
        x2v[2 * i + 1] = fmaxf(hi, 0.0f);
    }

    // ---- head: y = b2 + W2[0:32].x1 + W2[32:64].x2v (4 partial chains for ILP) ----
    const float* W2s = sM + 128;
    float s0 = sM[192], s1 = 0.0f, s2 = 0.0f, s3 = 0.0f;
#pragma unroll
    for (int i = 0; i < 32; i += 4) {
        s0 = fmaf(x1[i],     W2s[i],     s0);
        s1 = fmaf(x1[i + 1], W2s[i + 1], s1);
        s2 = fmaf(x1[i + 2], W2s[i + 2], s2);
        s3 = fmaf(x1[i + 3], W2s[i + 3], s3);
    }
#pragma unroll
    for (int i = 0; i < 32; i += 4) {
        s0 = fmaf(x2v[i],     W2s[32 + i],     s0);
        s1 = fmaf(x2v[i + 1], W2s[32 + i + 1], s1);
        s2 = fmaf(x2v[i + 2], W2s[32 + i + 2], s2);
        s3 = fmaf(x2v[i + 3], W2s[32 + i + 3], s3);
    }
    out[r0 + tid] = (s0 + s1) + (s2 + s3);
}

extern "C" void kernel_launch(void* const* d_in, const int* in_sizes, int n_in,
                              void* d_out, int out_size) {
    const float* pov   = (const float*)d_in[0];
    const float* white = (const float*)d_in[1];
    const float* black = (const float*)d_in[2];
    const float* Ww    = (const float*)d_in[3];
    const float* bw    = (const float*)d_in[4];
    const float* Wb    = (const float*)d_in[5];
    const float* bb    = (const float*)d_in[6];
    const float* W0    = (const float*)d_in[7];
    const float* b0    = (const float*)d_in[8];
    const float* W1    = (const float*)d_in[9];
    const float* b1    = (const float*)d_in[10];
    const float* W2    = (const float*)d_in[11];
    const float* b2    = (const float*)d_in[12];
    float* out = (float*)d_out;
    const int B = in_sizes[0];

    const int smem = (ROWSB * 99 + INW * 64 + 64 * 32 + 32 * 32 + 193) * (int)sizeof(float);
    cudaFuncSetAttribute(nnue_kernel, cudaFuncAttributeMaxDynamicSharedMemorySize, smem);

    prep_kernel<<<1, 256>>>(Ww, bw, Wb, bb, W0, b0, W1, b1, W2, b2);
    const int grid = (B + ROWSB - 1) / ROWSB;
    nnue_kernel<<<grid, TPB, smem>>>(pov, white, black, out, B);
}

// round 9
// speedup vs baseline: 1.6829x; 1.6829x over previous
#include <cuda_runtime.h>

// NNUE batched eval, register-blocked f32x2 version.
//   FT: X[B,98] @ Wcat[98,64]  (fused two half-GEMMs, columns pre-arranged)
//   warp tile: 128 rows x 16 cols; lane owns 4 rows (l, l+32, l+64, l+96),
//   8 u64 col-pair accumulators per row (64 regs). Weights via LDS.128
//   broadcast, reused across the 4 rows. Inputs staged in 4 k-chunks so
//   smem fits 4 blocks/SM (16 warps).

#define HALF 49
#define INW  98
#define TPB  128
#define ROWS 128
#define XPAD 27      // odd stride -> conflict-free per-lane x loads
#define FPAD 66      // even stride -> aligned STS.64 f stores (2-way ok)

// smem layout (float offsets)
#define OFF_XS   0                      // 128*27 = 3456 floats (chunk staging)
#define OFF_SW   3456                   // 98*64  = 6272 floats (FT weights)
#define OFF_FB   0                      // fbuf 128*66 = 8448 floats (overlays XS+SW after FT)
#define OFF_W0   9728                   // 2048 floats (u64-pair layout), 16B aligned
#define OFF_W1   (9728 + 2048)          // 1024 floats
#define OFF_SM   (9728 + 2048 + 1024)   // 193 floats misc
#define SMEM_FLOATS (9728 + 2048 + 1024 + 200)

// ---- __device__ scratch (allocation-free, prep kernel fills it) ----
__device__ float g_Wcat[INW * 64];   // [k][j] j<32: Ww col; j>=32: Wb col (halves swapped)
__device__ float g_W0t[64 * 32];     // [j][i] = W0[i][j]
__device__ float g_W1t[32 * 32];     // [j][i] = W1[i][j]
__device__ float g_misc[193];        // bcat[64], b0[32], b1[32], W2[64], b2[1]

__global__ void prep_kernel(const float* __restrict__ Ww, const float* __restrict__ bw,
                            const float* __restrict__ Wb, const float* __restrict__ bb,
                            const float* __restrict__ W0, const float* __restrict__ b0,
                            const float* __restrict__ W1, const float* __restrict__ b1,
                            const float* __restrict__ W2, const float* __restrict__ b2) {
    int t = threadIdx.x;
    for (int idx = t; idx < INW * 64; idx += blockDim.x) {
        int k = idx / 64, j = idx % 64;
        float v;
        if (j < 32) {
            v = Ww[j * INW + k];
        } else {
            int jj = j - 32;
            v = (k < HALF) ? Wb[jj * INW + k + HALF] : Wb[jj * INW + k - HALF];
        }
        g_Wcat[idx] = v;
    }
    for (int idx = t; idx < 64 * 32; idx += blockDim.x) {
        int j = idx / 32, i = idx % 32;
        g_W0t[idx] = W0[i * 64 + j];
    }
    for (int idx = t; idx < 32 * 32; idx += blockDim.x) {
        int j = idx / 32, i = idx % 32;
        g_W1t[idx] = W1[i * 32 + j];
    }
    for (int i = t; i < 193; i += blockDim.x) {
        float v;
        if (i < 32)        v = bw[i];
        else if (i < 64)   v = bb[i - 32];
        else if (i < 96)   v = b0[i - 64];
        else if (i < 128)  v = b1[i - 96];
        else if (i < 192)  v = W2[i - 128];
        else               v = b2[0];
        g_misc[i] = v;
    }
}

// ---- packed f32x2 helpers ----
#define PACK2F(dst, fa, fb) do {                                             \
    unsigned int _lo = __float_as_uint(fa), _hi = __float_as_uint(fb);       \
    asm("mov.b64 %0, {%1, %2};" : "=l"(dst) : "r"(_lo), "r"(_hi));           \
} while (0)

#define BCAST2F(dst, fa) do {                                                \
    unsigned int _v = __float_as_uint(fa);                                   \
    asm("mov.b64 %0, {%1, %1};" : "=l"(dst) : "r"(_v));                      \
} while (0)

#define UNPACK2F(fa, fb, src) do {                                           \
    unsigned int _lo, _hi;                                                   \
    asm("mov.b64 {%0, %1}, %2;" : "=r"(_lo), "=r"(_hi) : "l"(src));          \
    fa = __uint_as_float(_lo); fb = __uint_as_float(_hi);                    \
} while (0)

#define FMA2(acc, x2, w2) \
    asm("fma.rn.f32x2 %0, %1, %2, %0;" : "+l"(acc) : "l"(x2), "l"(w2))

// coalesced-ish k-chunk staging: thread strides over 128*LEN flat elements
template <int LEN>
__device__ __forceinline__ void stage_chunk(float* __restrict__ xs,
                                            const float* __restrict__ src,
                                            int r0, int kk0, int B, bool full) {
    for (int idx = threadIdx.x; idx < ROWS * LEN; idx += TPB) {
        int r = idx / LEN, kk = idx - r * LEN;
        float v = 0.0f;
        int gr = r0 + r;
        if (full || gr < B) v = src[(size_t)gr * HALF + kk0 + kk];
        xs[r * XPAD + kk] = v;
    }
}

// FT accumulate over one k-chunk. Lane owns rows {lane + 32*rr}, cols
// [colbase, colbase+16) as 8 u64 pairs per row.
template <int LEN>
__device__ __forceinline__ void ft_chunk(const float* __restrict__ sh,
                                         unsigned long long acc[4][8],
                                         int lane, int colbase, int kbase) {
    const float* xb = sh + OFF_XS + lane * XPAD;
    const float* wb = sh + OFF_SW + kbase * 64 + colbase;
#pragma unroll 4
    for (int kk = 0; kk < LEN; kk++) {
        const ulonglong2* wp = reinterpret_cast<const ulonglong2*>(wb + kk * 64);
        ulonglong2 w0 = wp[0], w1 = wp[1], w2 = wp[2], w3 = wp[3];
#pragma unroll
        for (int rr = 0; rr < 4; rr++) {
            unsigned long long x2;
            BCAST2F(x2, xb[rr * (32 * XPAD) + kk]);
            FMA2(acc[rr][0], x2, w0.x); FMA2(acc[rr][1], x2, w0.y);
            FMA2(acc[rr][2], x2, w1.x); FMA2(acc[rr][3], x2, w1.y);
            FMA2(acc[rr][4], x2, w2.x); FMA2(acc[rr][5], x2, w2.y);
            FMA2(acc[rr][6], x2, w3.x); FMA2(acc[rr][7], x2, w3.y);
        }
    }
}

__global__ __launch_bounds__(TPB, 4)
void nnue_kernel(const float* __restrict__ pov,
                 const float* __restrict__ white,
                 const float* __restrict__ black,
                 float* __restrict__ out, int B) {
    extern __shared__ float sh[];
    const int tid  = threadIdx.x;
    const int wid  = tid >> 5;
    const int lane = tid & 31;
    const int r0   = blockIdx.x * ROWS;
    const bool full = (r0 + ROWS <= B);
    const int colbase = wid * 16;

    // early global reads (overlap with staging)
    float p_pov = 0.0f;
    if (full || r0 + tid < B) p_pov = pov[r0 + tid];

    // stage weights once
    for (int i = tid; i < INW * 64; i += TPB) sh[OFF_SW + i] = g_Wcat[i];
    for (int i = tid; i < 64 * 32;  i += TPB) sh[OFF_W0 + i] = g_W0t[i];
    for (int i = tid; i < 32 * 32;  i += TPB) sh[OFF_W1 + i] = g_W1t[i];
    for (int i = tid; i < 193;      i += TPB) sh[OFF_SM + i] = g_misc[i];

    // init accumulators with biases (same pair for all 4 rows)
    unsigned long long acc[4][8];
#pragma unroll
    for (int c = 0; c < 8; c++) {
        unsigned long long bpair;
        PACK2F(bpair, g_misc[colbase + 2 * c], g_misc[colbase + 2 * c + 1]);
#pragma unroll
        for (int rr = 0; rr < 4; rr++) acc[rr][c] = bpair;
    }

    // ---- feature transform in 4 k-chunks ----
    __syncthreads();
    stage_chunk<25>(sh + OFF_XS, white, r0, 0, B, full);
    __syncthreads();
    ft_chunk<25>(sh, acc, lane, colbase, 0);
    __syncthreads();
    stage_chunk<24>(sh + OFF_XS, white, r0, 25, B, full);
    __syncthreads();
    ft_chunk<24>(sh, acc, lane, colbase, 25);
    __syncthreads();
    stage_chunk<25>(sh + OFF_XS, black, r0, 0, B, full);
    __syncthreads();
    ft_chunk<25>(sh, acc, lane, colbase, 49);
    __syncthreads();
    stage_chunk<24>(sh + OFF_XS, black, r0, 25, B, full);
    __syncthreads();
    ft_chunk<24>(sh, acc, lane, colbase, 74);

    // ---- cross-warp exchange: write f to fbuf (overlays xs+sW) ----
    __syncthreads();
#pragma unroll
    for (int rr = 0; rr < 4; rr++) {
        unsigned long long* dst = reinterpret_cast<unsigned long long*>(
            sh + OFF_FB + (lane + 32 * rr) * FPAD + colbase);
#pragma unroll
        for (int c = 0; c < 8; c++) dst[c] = acc[rr][c];
    }
    __syncthreads();

    // ---- tail: 1 thread = 1 row, f from fbuf ----
    if (full || r0 + tid < B) {
        const float* fb = sh + OFF_FB + tid * FPAD;
        const float p = p_pov, q = 1.0f - p_pov;
        const float* sM = sh + OFF_SM;

        // L0 fused with blend: a0[i] (16 u64 = 32 outs)
        unsigned long long a0[16];
#pragma unroll
        for (int i = 0; i < 16; i++) PACK2F(a0[i], sM[64 + 2 * i], sM[64 + 2 * i + 1]);
        const ulonglong2* W0q = reinterpret_cast<const ulonglong2*>(sh + OFF_W0);
#pragma unroll 4
        for (int j = 0; j < 32; j++) {
            float fw = fb[j], fbl = fb[32 + j];
            float bj  = fmaxf(fmaf(p, fw, q * fbl), 0.0f);
            float bj2 = fmaxf(fmaf(p, fbl, q * fw), 0.0f);
            unsigned long long xa, xb2;
            BCAST2F(xa, bj); BCAST2F(xb2, bj2);
            const ulonglong2* wa = W0q + j * 8;
            const ulonglong2* wb = W0q + (j + 32) * 8;
#pragma unroll
            for (int t = 0; t < 8; t++) {
                ulonglong2 wv = wa[t];
                FMA2(a0[2 * t], xa, wv.x); FMA2(a0[2 * t + 1], xa, wv.y);
            }
#pragma unroll
            for (int t = 0; t < 8; t++) {
                ulonglong2 wv = wb[t];
                FMA2(a0[2 * t], xb2, wv.x); FMA2(a0[2 * t + 1], xb2, wv.y);
            }
        }
        float x1[32];
#pragma unroll
        for (int i = 0; i < 16; i++) {
            float lo, hi; UNPACK2F(lo, hi, a0[i]);
            x1[2 * i]     = fmaxf(lo, 0.0f);
            x1[2 * i + 1] = fmaxf(hi, 0.0f);
        }

        // L1: x2v = relu(W1 @ x1 + b1)
        unsigned long long a1[16];
#pragma unroll
        for (int i = 0; i < 16; i++) PACK2F(a1[i], sM[96 + 2 * i], sM[96 + 2 * i + 1]);
        const ulonglong2* W1q = reinterpret_cast<const ulonglong2*>(sh + OFF_W1);
#pragma unroll 4
        for (int j = 0; j < 32; j++) {
            unsigned long long x2;
            BCAST2F(x2, x1[j]);
            const ulonglong2* wv = W1q + j * 8;
#pragma unroll
            for (int t = 0; t < 8; t++) {
                ulonglong2 w = wv[t];
                FMA2(a1[2 * t], x2, w.x); FMA2(a1[2 * t + 1], x2, w.y);
            }
        }
        float x2v[32];
#pragma unroll
        for (int i = 0; i < 16; i++) {
            float lo, hi; UNPACK2F(lo, hi, a1[i]);
            x2v[2 * i]     = fmaxf(lo, 0.0f);
            x2v[2 * i + 1] = fmaxf(hi, 0.0f);
        }

        // head: y = b2 + W2[0:32].x1 + W2[32:64].x2v
        const float* W2s = sM + 128;
        float s0 = sM[192], s1 = 0.0f, s2 = 0.0f, s3 = 0.0f;
#pragma unroll
        for (int i = 0; i < 32; i += 4) {
            s0 = fmaf(x1[i],     W2s[i],     s0);
            s1 = fmaf(x1[i + 1], W2s[i + 1], s1);
            s2 = fmaf(x1[i + 2], W2s[i + 2], s2);
            s3 = fmaf(x1[i + 3], W2s[i + 3], s3);
        }
#pragma unroll
        for (int i = 0; i < 32; i += 4) {
            s0 = fmaf(x2v[i],     W2s[32 + i],     s0);
            s1 = fmaf(x2v[i + 1], W2s[32 + i + 1], s1);
            s2 = fmaf(x2v[i + 2], W2s[32 + i + 2], s2);
            s3 = fmaf(x2v[i + 3], W2s[32 + i + 3], s3);
        }
        out[r0 + tid] = (s0 + s1) + (s2 + s3);
    }
}

extern "C" void kernel_launch(void* const* d_in, const int* in_sizes, int n_in,
                              void* d_out, int out_size) {
    const float* pov   = (const float*)d_in[0];
    const float* white = (const float*)d_in[1];
    const float* black = (const float*)d_in[2];
    const float* Ww    = (const float*)d_in[3];
    const float* bw    = (const float*)d_in[4];
    const float* Wb    = (const float*)d_in[5];
    const float* bb    = (const float*)d_in[6];
    const float* W0    = (const float*)d_in[7];
    const float* b0    = (const float*)d_in[8];
    const float* W1    = (const float*)d_in[9];
    const float* b1    = (const float*)d_in[10];
    const float* W2    = (const float*)d_in[11];
    const float* b2    = (const float*)d_in[12];
    float* out = (float*)d_out;
    const int B = in_sizes[0];

    const int smem = SMEM_FLOATS * (int)sizeof(float);
    cudaFuncSetAttribute(nnue_kernel, cudaFuncAttributeMaxDynamicSharedMemorySize, smem);

    prep_kernel<<<1, 256>>>(Ww, bw, Wb, bb, W0, b0, W1, b1, W2, b2);
    const int grid = (B + ROWS - 1) / ROWS;
    nnue_kernel<<<grid, TPB, smem>>>(pov, white, black, out, B);
}